// round 14
// baseline (speedup 1.0000x reference)
#include <cuda_runtime.h>
#include <math.h>

#define Bc 8
#define Sc 512
#define Nc (Sc*Sc)
#define ITERS 20
#define EPSF 1e-6f
#define INVH 511.0f
#define HF (1.0f/511.0f)
#define HH (HF*HF)
#define INVH2 (511.0f*511.0f)
#define GAMMA_F 10.0f
#define THRESH_F 0.5f

// persistent kernel config: 296 = 2*148 blocks
#define PT 512
#define BPB 37
#define PB (Bc*BPB)
#define RMAX 14
#define NW 16              // warps per block

// ---- scratch ----
__device__ float2 g_cf[Bc*Nc];          // packed (cx_north, cy_east) * 1/h^2
__device__ float g_lap[Bc*Nc];
__device__ float g_rho[Bc*Nc];
__device__ float g_P[Bc*Nc];
__device__ float g_Q[Bc*Nc];
__device__ float g_BB[Bc*Nc];
__device__ float g_BNX[Bc*Nc];
__device__ float g_BNY[Bc*Nc];
__device__ float g_RB[Nc];
__device__ float g_r[Bc*Nc];
__device__ float g_wbuf[2][Bc*Nc];      // double-buffered w halo (edge rows only)
__device__ float2 g_part[Bc*BPB];
__device__ unsigned g_cnt[Bc];
__device__ unsigned long long g_pubA[Bc];
__device__ unsigned long long g_pubB[Bc];

// =====================================================================
// S1: per-cell precompute (4 rows/block, smem log tiles)
// =====================================================================
__global__ void __launch_bounds__(512)
s1_kernel(const float* __restrict__ coeff,
          const float* __restrict__ u,
          const float* __restrict__ beta) {
    __shared__ float sC[6][Sc];
    __shared__ float sL[6][Sc];
    __shared__ float sU[6][Sc];
    int b = blockIdx.y;
    int r0 = blockIdx.x * 4;
    int t = threadIdx.x;
    size_t off = (size_t)b * Nc;
    const float4* B4 = (const float4*)beta + off;

    for (int rr = 0; rr < 6; rr++) {
        int i = r0 - 1 + rr;
        bool in = (i >= 0 && i < Sc);
        float c = in ? coeff[off + (size_t)i*Sc + t] : 0.f;
        float uu = in ? u[off + (size_t)i*Sc + t] : 0.f;
        sC[rr][t] = c;
        sU[rr][t] = uu;
        sL[rr][t] = logf(fmaxf(c, EPSF));
    }
    __syncthreads();

#pragma unroll
    for (int k = 0; k < 4; k++) {
        int i = r0 + k;
        int w = k + 1;
        int idx = i*Sc + t;
        float c = sC[w][t];

        float cfx = 0.f, cfy = 0.f;
        if (i < Sc-1) { float cn = sC[w+1][t]; cfx = (2.f*c*cn / (c + cn + EPSF)) * INVH2; }
        if (t < Sc-1) { float ce = sC[w][t+1]; cfy = (2.f*c*ce / (c + ce + EPSF)) * INVH2; }
        g_cf[off+idx] = make_float2(cfx, cfy);

        float lap = 0.f;
        bool interior = (i > 0 && i < Sc-1 && t > 0 && t < Sc-1);
        if (interior) {
            float uc = sU[w][t];
            lap = ((sU[w+1][t]-uc)*INVH - (uc-sU[w-1][t])*INVH)*INVH
                + ((sU[w][t+1]-uc)*INVH - (uc-sU[w][t-1])*INVH)*INVH;
        }
        g_lap[off+idx] = lap;

        float lc = sL[w][t];
        float glx, gly;
        if (i == 0)          glx = (sL[w+1][t] - lc) * INVH;
        else if (i == Sc-1)  glx = (lc - sL[w-1][t]) * INVH;
        else                 glx = (sL[w+1][t] - sL[w-1][t]) * (0.5f*INVH);
        if (t == 0)          gly = (sL[w][t+1] - lc) * INVH;
        else if (t == Sc-1)  gly = (lc - sL[w][t-1]) * INVH;
        else                 gly = (sL[w][t+1] - sL[w][t-1]) * (0.5f*INVH);

        float eta = sqrtf(glx*glx + gly*gly + EPSF);
        float rho = 1.f / (1.f + expf(-GAMMA_F * (eta - THRESH_F)));
        float nhx = glx / eta, nhy = gly / eta;

        float4 bv = B4[idx];
        g_rho[off+idx] = rho;
        g_P[off+idx]   = bv.y*nhx - bv.z*nhy;
        g_Q[off+idx]   = bv.y*nhy + bv.z*nhx;
        g_BB[off+idx]  = bv.x;

        float bnx, bny, dd;
        if (i + t != 511) {
            int m0 = i, m1 = 511-i, m2 = t, m3 = 511-t;
            int best = m0, kk = 0;
            if (m1 < best) { best = m1; kk = 1; }
            if (m2 < best) { best = m2; kk = 2; }
            if (m3 < best) { best = m3; kk = 3; }
            bnx = (kk == 0) ? -1.f : ((kk == 1) ? 1.f : 0.f);
            bny = (kk == 2) ? -1.f : ((kk == 3) ? 1.f : 0.f);
            dd = (float)((double)best * (1.0/511.0));
        } else {
            double dl = 1.0 / 511.0;
            double xx = (i == Sc-1) ? 1.0 : (double)i * dl;
            double yy = (t == Sc-1) ? 1.0 : (double)t * dl;
            double a0 = xx, a1 = 1.0 - xx, a2 = yy, a3 = 1.0 - yy;
            double best = a0; int kk = 0;
            if (a1 < best) { best = a1; kk = 1; }
            if (a2 < best) { best = a2; kk = 2; }
            if (a3 < best) { best = a3; kk = 3; }
            bnx = (kk == 0) ? -1.f : ((kk == 1) ? 1.f : 0.f);
            bny = (kk == 2) ? -1.f : ((kk == 3) ? 1.f : 0.f);
            dd = (float)best;
        }
        g_BNX[off+idx] = bv.w * bnx;
        g_BNY[off+idx] = bv.w * bny;
        if (b == 0) g_RB[idx] = expf(-(dd*dd) / (0.15f*0.15f));
    }
}

// =====================================================================
// S2: rhs -> g_r
// =====================================================================
#define NBs 128
#define TPBs 256
#define CPBs (Nc/NBs)

__device__ __forceinline__ float fluxX(const float* C, const float* U, const float* LAP,
                                       const float* RHO, const float* PP, const float* BB,
                                       const float* BNX, int a) {
    int b2 = a + Sc;
    float ca = C[a], cb = C[b2];
    float cxf = 2.f*ca*cb / (ca + cb + EPSF);
    float gux = (U[b2] - U[a]) * INVH;
    float lgx = (LAP[b2] - LAP[a]) * INVH;
    return 0.5f*(BB[a]+BB[b2]) * HH * cxf * lgx
         + 0.5f*(RHO[a]+RHO[b2]) * (0.5f*(PP[a]+PP[b2])) * cxf * gux
         + 0.5f*(g_RB[a]+g_RB[b2]) * (0.5f*(BNX[a]+BNX[b2])) * cxf * gux;
}

__device__ __forceinline__ float fluxY(const float* C, const float* U, const float* LAP,
                                       const float* RHO, const float* QQ, const float* BB,
                                       const float* BNY, int a) {
    int b2 = a + 1;
    float ca = C[a], cb = C[b2];
    float cyf = 2.f*ca*cb / (ca + cb + EPSF);
    float guy = (U[b2] - U[a]) * INVH;
    float lgy = (LAP[b2] - LAP[a]) * INVH;
    return 0.5f*(BB[a]+BB[b2]) * HH * cyf * lgy
         + 0.5f*(RHO[a]+RHO[b2]) * (0.5f*(QQ[a]+QQ[b2])) * cyf * guy
         + 0.5f*(g_RB[a]+g_RB[b2]) * (0.5f*(BNY[a]+BNY[b2])) * cyf * guy;
}

__global__ void s2_kernel(const float* __restrict__ coeff, const float* __restrict__ u) {
    int b = blockIdx.y;
    size_t off = (size_t)b * Nc;
    const float* C = coeff + off;
    const float* U = u + off;
    const float* LAP = g_lap + off;
    const float* RHO = g_rho + off;
    const float* PP  = g_P + off;
    const float* QQ  = g_Q + off;
    const float* BB  = g_BB + off;
    const float* BNX = g_BNX + off;
    const float* BNY = g_BNY + off;
    int base = blockIdx.x * CPBs;

    for (int t = threadIdx.x; t < CPBs; t += TPBs) {
        int idx = base + t;
        int i = idx >> 9;
        int j = idx & (Sc - 1);
        float rhs = 0.f;
        if (i > 0 && i < Sc-1 && j > 0 && j < Sc-1) {
            float fxN = fluxX(C, U, LAP, RHO, PP, BB, BNX, idx);
            float fxS = fluxX(C, U, LAP, RHO, PP, BB, BNX, idx - Sc);
            float fyE = fluxY(C, U, LAP, RHO, QQ, BB, BNY, idx);
            float fyW = fluxY(C, U, LAP, RHO, QQ, BB, BNY, idx - 1);
            rhs = (fxN - fxS) * INVH + (fyE - fyW) * INVH;
        }
        g_r[off+idx] = rhs;
    }
}

__global__ void zc_kernel() {
    if (threadIdx.x < Bc) {
        g_cnt[threadIdx.x] = 0u;
        g_pubA[threadIdx.x] = 0ull;
        g_pubB[threadIdx.x] = 0ull;
    }
}

// =====================================================================
// one barrier: deterministic reduction of two dots + fence
// =====================================================================
__device__ __forceinline__ float2 sync_reduce2(float va, float vb, float* sRed,
                                               int b, int rblk, unsigned ev) {
#pragma unroll
    for (int o = 16; o > 0; o >>= 1) {
        va += __shfl_down_sync(0xffffffffu, va, o);
        vb += __shfl_down_sync(0xffffffffu, vb, o);
    }
    if ((threadIdx.x & 31) == 0) {
        sRed[2*(threadIdx.x >> 5)]   = va;
        sRed[2*(threadIdx.x >> 5)+1] = vb;
    }
    __syncthreads();
    if (threadIdx.x == 0) {
        float sa = 0.f, sb = 0.f;
#pragma unroll
        for (int w = 0; w < 16; w++) { sa += sRed[2*w]; sb += sRed[2*w+1]; }
        g_part[b*BPB + rblk] = make_float2(sa, sb);
        unsigned old;
        asm volatile("atom.acq_rel.gpu.global.add.u32 %0, [%1], %2;"
                     : "=r"(old) : "l"(&g_cnt[b]), "r"(1u) : "memory");
        if (old == ev*BPB - 1u) {
            const float2* pp = &g_part[b*BPB];
            float ga = 0.f, gb2 = 0.f;
#pragma unroll
            for (int i = 0; i < BPB; i++) { float2 v = pp[i]; ga += v.x; gb2 += v.y; }
            unsigned long long pkA = ((unsigned long long)ev << 32) |
                                     (unsigned long long)__float_as_uint(ga);
            unsigned long long pkB = ((unsigned long long)ev << 32) |
                                     (unsigned long long)__float_as_uint(gb2);
            asm volatile("st.release.gpu.global.b64 [%0], %1;" :: "l"(&g_pubA[b]), "l"(pkA) : "memory");
            asm volatile("st.release.gpu.global.b64 [%0], %1;" :: "l"(&g_pubB[b]), "l"(pkB) : "memory");
            sRed[0] = ga; sRed[1] = gb2;
        } else {
            unsigned long long pk;
            do {
                asm volatile("ld.acquire.gpu.global.b64 %0, [%1];"
                             : "=l"(pk) : "l"(&g_pubB[b]) : "memory");
            } while ((unsigned)(pk >> 32) != ev);
            sRed[1] = __uint_as_float((unsigned)pk);
            do {
                asm volatile("ld.acquire.gpu.global.b64 %0, [%1];"
                             : "=l"(pk) : "l"(&g_pubA[b]) : "memory");
            } while ((unsigned)(pk >> 32) != ev);
            sRed[0] = __uint_as_float((unsigned)pk);
        }
    }
    __syncthreads();
    float2 r = make_float2(sRed[0], sRed[1]);
    __syncthreads();
    return r;
}

#define EDGE_FLOATS (NW*RMAX*2)
#define SMEM_FLOATS (3*RMAX*PT + 64 + 2*EDGE_FLOATS)
#define SMEM_BYTES (SMEM_FLOATS * 4)

// =====================================================================
// Persistent PIPECG: single fused pass/iter; w,r,p in registers,
// horizontal w via shfl + double-buffered warp-edge smem.
// =====================================================================
__global__ void __launch_bounds__(PT, 2)
cg_kernel(const float* __restrict__ u, float* __restrict__ out) {
    extern __shared__ float sm[];
    float* sS    = sm;                    // s = A p    (own-cell only)
    float* sZ    = sm + RMAX*PT;          // z = A s    (own-cell only)
    float* sX    = sm + 2*RMAX*PT;        // x          (own-cell only)
    float* sRed  = sm + 3*RMAX*PT;        // 64 floats
    float* sEdge = sRed + 64;             // [2][NW][RMAX][2]

    const int t = threadIdx.x;
    const int lane = t & 31;
    const int wid = t >> 5;
    const int blk = blockIdx.x;
    const int b = blk / BPB;
    const int rblk = blk - b*BPB;
    const int start = (rblk < 31) ? rblk*14 : 434 + (rblk-31)*13;
    const int nr = (rblk < 31) ? 14 : 13;
    const size_t off = (size_t)b * Nc;
    const size_t gb = off + (size_t)start * Sc + t;
    const float2* __restrict__ CF = g_cf + off;
    unsigned ev = 0;

    const bool interiorT = (t > 0 && t < Sc-1);
    const int tcy = (t > 0) ? t-1 : 0;
    const int widE = (wid < NW-1) ? wid+1 : wid;   // t=511 masked anyway
    const int widW = (wid > 0) ? wid-1 : wid;      // t=0 masked anyway
    float r[RMAX], p[RMAX], w[RMAX];

    // ---- init: load r (stage through sS for horizontal), w0 = A r0, dots ----
#pragma unroll
    for (int k = 0; k < RMAX; k++) {
        bool act = (k < nr);
        float rv = act ? g_r[gb + k*Sc] : 0.f;
        r[k] = rv;
        sS[k*PT + t] = rv;
        p[k] = 0.f;
    }
    __syncthreads();

    float accA = 0.f, accB = 0.f;
    {
        float rHT = (rblk > 0)     ? g_r[gb - Sc]     : 0.f;
        float rHB = (rblk < BPB-1) ? g_r[gb + nr*Sc]  : 0.f;
        float cxp = CF[(size_t)(start > 0 ? start-1 : 0)*Sc + t].x;
        float* sEw = sEdge;   // buffer 0
#pragma unroll
        for (int k = 0; k < RMAX; k++) {
            bool act = (k < nr);
            int i = start + k;
            int ii = act ? i : Sc-1;
            float2 cf = CF[(size_t)ii*Sc + t];
            float cye = cf.y;
            float cyw = __shfl_up_sync(0xffffffffu, cye, 1);
            if (lane == 0) cyw = CF[(size_t)ii*Sc + tcy].y;
            float wv = 0.f;
            if (act && i > 0 && i < Sc-1 && interiorT) {
                float rc = r[k];
                float ru = (k == nr-1) ? rHB : sS[(k+1)*PT + t];
                float rd = (k == 0)    ? rHT : sS[(k-1)*PT + t];
                float re = sS[k*PT + t + 1];
                float rw_ = sS[k*PT + t - 1];
                wv = cf.x*(rc-ru) + cxp*(rc-rd) + cye*(rc-re) + cyw*(rc-rw_);
            }
            w[k] = wv;
            accA += r[k]*r[k];
            accB += wv*r[k];
            if (act && (k == 0 || k == nr-1)) g_wbuf[0][gb + k*Sc] = wv;
            if (lane == 0 || lane == 31)
                sEw[wid*RMAX*2 + k*2 + (lane == 31 ? 1 : 0)] = wv;
            cxp = cf.x;
        }
    }
    __syncthreads();      // all sS staging reads done
#pragma unroll
    for (int k = 0; k < RMAX; k++) {   // own-cell fields: no cross-thread hazard
        sS[k*PT + t] = 0.f;
        sZ[k*PT + t] = 0.f;
        sX[k*PT + t] = 0.f;
    }

    float gamma_old = 1.f, alpha_old = 1.f;

    for (int it = 0; it < ITERS; it++) {
        ev++;
        float2 gd = sync_reduce2(accA, accB, sRed, b, rblk, ev);
        float G = gd.x, D = gd.y;
        float beta, alpha;
        if (it == 0) {
            beta = 0.f;
            alpha = G / fmaxf(D, EPSF);
        } else {
            beta = G / fmaxf(gamma_old, EPSF);
            float den = D - beta * G / alpha_old;
            alpha = G / fmaxf(den, EPSF);
        }

        if (it == ITERS-1) {
#pragma unroll
            for (int k = 0; k < RMAX; k++) {
                float pv = r[k] + beta * p[k];
                sX[k*PT + t] += alpha * pv;
            }
            break;
        }

        // ---- fused pass: q = A w_old; all recurrences; next dots ----
        int par = it & 1;
        const float* sEr = sEdge + par * EDGE_FLOATS;
        float* sEw = sEdge + (par ^ 1) * EDGE_FLOATS;
        const float* gwr = g_wbuf[par];
        float* gww = g_wbuf[par ^ 1];

        float wHT = (rblk > 0)     ? gwr[gb - Sc]     : 0.f;
        float wHB = (rblk < BPB-1) ? gwr[gb + nr*Sc]  : 0.f;
        float cxp = CF[(size_t)(start > 0 ? start-1 : 0)*Sc + t].x;
        float wpo = wHT;   // old w at row k-1
        accA = 0.f; accB = 0.f;
#pragma unroll
        for (int k = 0; k < RMAX; k++) {
            bool act = (k < nr);
            int i = start + k;
            int ii = act ? i : Sc-1;
            float2 cf = CF[(size_t)ii*Sc + t];
            float cye = cf.y;
            float cyw = __shfl_up_sync(0xffffffffu, cye, 1);
            if (lane == 0) cyw = CF[(size_t)ii*Sc + tcy].y;

            float wold = w[k];
            float wno = (k == nr-1) ? wHB : w[k+1 < RMAX ? k+1 : k];  // old w north (not yet updated)
            float we = __shfl_down_sync(0xffffffffu, wold, 1);
            float ww = __shfl_up_sync(0xffffffffu, wold, 1);
            if (lane == 31) we = sEr[widE*RMAX*2 + k*2];
            if (lane == 0)  ww = sEr[widW*RMAX*2 + k*2 + 1];

            float q = 0.f;
            if (act && i > 0 && i < Sc-1 && interiorT)
                q = cf.x*(wold-wno) + cxp*(wold-wpo) + cye*(wold-we) + cyw*(wold-ww);

            float z = q + beta * sZ[k*PT + t];
            sZ[k*PT + t] = z;
            float s = wold + beta * sS[k*PT + t];
            sS[k*PT + t] = s;
            float pv = r[k] + beta * p[k];
            p[k] = pv;
            sX[k*PT + t] += alpha * pv;
            float rv = r[k] - alpha * s;
            r[k] = rv;
            float wnew = wold - alpha * z;
            w[k] = wnew;
            accA += rv * rv;
            accB += wnew * rv;

            if (act && (k == 0 || k == nr-1)) gww[gb + k*Sc] = wnew;
            if (lane == 0 || lane == 31)
                sEw[wid*RMAX*2 + k*2 + (lane == 31 ? 1 : 0)] = wnew;

            wpo = wold;
            cxp = cf.x;
        }
        gamma_old = G;
        alpha_old = alpha;
        // next sync_reduce2's __syncthreads orders sEdge writes vs reads
    }

    // ---- output: out = zb(u + x) ----
#pragma unroll
    for (int k = 0; k < RMAX; k++) {
        if (k >= nr) continue;
        int i = start + k;
        size_t gi = gb + k*Sc;
        float v = 0.f;
        if (i > 0 && i < Sc-1 && interiorT) v = u[gi] + sX[k*PT + t];
        out[gi] = v;
    }
}

extern "C" void kernel_launch(void* const* d_in, const int* in_sizes, int n_in,
                              void* d_out, int out_size) {
    const float* coeff = (const float*)d_in[0];
    const float* u     = (const float*)d_in[1];
    const float* beta  = (const float*)d_in[2];
    float* out = (float*)d_out;

    cudaFuncSetAttribute(cg_kernel, cudaFuncAttributeMaxDynamicSharedMemorySize, SMEM_BYTES);

    zc_kernel<<<1, 32>>>();
    dim3 g1(128, Bc);
    s1_kernel<<<g1, 512>>>(coeff, u, beta);
    dim3 g2(NBs, Bc);
    s2_kernel<<<g2, TPBs>>>(coeff, u);
    cg_kernel<<<PB, PT, SMEM_BYTES>>>(u, out);
}

// round 15
// speedup vs baseline: 1.0789x; 1.0789x over previous
#include <cuda_runtime.h>
#include <math.h>

#define Bc 8
#define Sc 512
#define Nc (Sc*Sc)
#define ITERS 20
#define EPSF 1e-6f
#define INVH 511.0f
#define HF (1.0f/511.0f)
#define HH (HF*HF)
#define INVH2 (511.0f*511.0f)
#define GAMMA_F 10.0f
#define THRESH_F 0.5f

// persistent CG config: 296 = 2*148 blocks
#define PT 512
#define BPB 37
#define PB (Bc*BPB)
#define RMAX 14

// fused setup config
#define SR 4                    // output rows per block

// ---- scratch ----
__device__ float2 g_cf[Bc*Nc];          // packed (cx_north, cy_east) * 1/h^2
__device__ float g_r[Bc*Nc];
__device__ float g_w[Bc*Nc];            // edge rows only during CG
__device__ float2 g_part[Bc*BPB];
__device__ unsigned g_cnt[Bc];
__device__ unsigned long long g_pubA[Bc];
__device__ unsigned long long g_pubB[Bc];

// =====================================================================
// Fused setup: per-cell fields in smem tiles -> g_cf + g_r directly.
// Block covers SR output rows; needs rows r0-2..r0+SR+1 of u/coeff,
// rows r0-1..r0+SR of derived cell fields.
// =====================================================================
#define T8 (SR+4)
#define T6 (SR+2)
#define SF_FLOATS ((3*T8 + 8*T6) * Sc)
#define SF_BYTES (SF_FLOATS * 4)

__global__ void __launch_bounds__(512)
sf_kernel(const float* __restrict__ coeff,
          const float* __restrict__ u,
          const float* __restrict__ beta) {
    extern __shared__ float sbuf[];
    float* sC   = sbuf;                  // [T8][Sc]
    float* sU   = sC   + T8*Sc;
    float* sL   = sU   + T8*Sc;
    float* sLap = sL   + T8*Sc;          // [T6][Sc]
    float* sRho = sLap + T6*Sc;
    float* sPP  = sRho + T6*Sc;
    float* sQQ  = sPP  + T6*Sc;
    float* sBB  = sQQ  + T6*Sc;
    float* sBNX = sBB  + T6*Sc;
    float* sBNY = sBNX + T6*Sc;
    float* sRB  = sBNY + T6*Sc;

    int b = blockIdx.y;
    int r0 = blockIdx.x * SR;
    int t = threadIdx.x;
    size_t off = (size_t)b * Nc;
    const float4* B4 = (const float4*)beta + off;

    // barrier-state reset for the CG kernel (replaces zc kernel)
    if (b == 0 && blockIdx.x == 0 && t < Bc) {
        g_cnt[t] = 0u; g_pubA[t] = 0ull; g_pubB[t] = 0ull;
    }

    // ---- stage u, coeff, log(coeff) ----
#pragma unroll
    for (int rr = 0; rr < T8; rr++) {
        int i = r0 - 2 + rr;
        bool in = (i >= 0 && i < Sc);
        float c  = in ? coeff[off + (size_t)i*Sc + t] : 1.f;
        float uu = in ? u[off + (size_t)i*Sc + t] : 0.f;
        sC[rr*Sc + t] = c;
        sU[rr*Sc + t] = uu;
        sL[rr*Sc + t] = logf(fmaxf(c, EPSF));
    }
    __syncthreads();

    // ---- per-cell derived fields for rows r0-1 .. r0+SR ----
#pragma unroll
    for (int rr = 1; rr <= SR+2; rr++) {
        int i = r0 - 2 + rr;
        int w6 = rr - 1;
        bool vi = (i >= 0 && i < Sc);
        float lap = 0.f, rho = 0.f, pP = 0.f, qQ = 0.f, bb = 0.f;
        float bnxv = 0.f, bnyv = 0.f, rbv = 0.f;
        if (vi) {
            bool interior = (i > 0 && i < Sc-1 && t > 0 && t < Sc-1);
            if (interior) {
                float uc = sU[rr*Sc + t];
                lap = ((sU[(rr+1)*Sc+t]-uc)*INVH - (uc-sU[(rr-1)*Sc+t])*INVH)*INVH
                    + ((sU[rr*Sc+t+1]-uc)*INVH - (uc-sU[rr*Sc+t-1])*INVH)*INVH;
            }
            float lc = sL[rr*Sc + t];
            float glx, gly;
            if (i == 0)          glx = (sL[(rr+1)*Sc+t] - lc) * INVH;
            else if (i == Sc-1)  glx = (lc - sL[(rr-1)*Sc+t]) * INVH;
            else                 glx = (sL[(rr+1)*Sc+t] - sL[(rr-1)*Sc+t]) * (0.5f*INVH);
            if (t == 0)          gly = (sL[rr*Sc+t+1] - lc) * INVH;
            else if (t == Sc-1)  gly = (lc - sL[rr*Sc+t-1]) * INVH;
            else                 gly = (sL[rr*Sc+t+1] - sL[rr*Sc+t-1]) * (0.5f*INVH);

            float eta = sqrtf(glx*glx + gly*gly + EPSF);
            rho = 1.f / (1.f + expf(-GAMMA_F * (eta - THRESH_F)));
            float nhx = glx / eta, nhy = gly / eta;

            float4 bv = B4[(size_t)i*Sc + t];
            pP = bv.y*nhx - bv.z*nhy;
            qQ = bv.y*nhy + bv.z*nhx;
            bb = bv.x;

            float bnx, bny, dd;
            if (i + t != 511) {
                int m0 = i, m1 = 511-i, m2 = t, m3 = 511-t;
                int best = m0, kk = 0;
                if (m1 < best) { best = m1; kk = 1; }
                if (m2 < best) { best = m2; kk = 2; }
                if (m3 < best) { best = m3; kk = 3; }
                bnx = (kk == 0) ? -1.f : ((kk == 1) ? 1.f : 0.f);
                bny = (kk == 2) ? -1.f : ((kk == 3) ? 1.f : 0.f);
                dd = (float)((double)best * (1.0/511.0));
            } else {
                double dl = 1.0 / 511.0;
                double xx = (i == Sc-1) ? 1.0 : (double)i * dl;
                double yy = (t == Sc-1) ? 1.0 : (double)t * dl;
                double a0 = xx, a1 = 1.0 - xx, a2 = yy, a3 = 1.0 - yy;
                double best = a0; int kk = 0;
                if (a1 < best) { best = a1; kk = 1; }
                if (a2 < best) { best = a2; kk = 2; }
                if (a3 < best) { best = a3; kk = 3; }
                bnx = (kk == 0) ? -1.f : ((kk == 1) ? 1.f : 0.f);
                bny = (kk == 2) ? -1.f : ((kk == 3) ? 1.f : 0.f);
                dd = (float)best;
            }
            bnxv = bv.w * bnx;
            bnyv = bv.w * bny;
            rbv  = expf(-(dd*dd) / (0.15f*0.15f));
        }
        sLap[w6*Sc+t] = lap;  sRho[w6*Sc+t] = rho;
        sPP[w6*Sc+t]  = pP;   sQQ[w6*Sc+t]  = qQ;
        sBB[w6*Sc+t]  = bb;   sBNX[w6*Sc+t] = bnxv;
        sBNY[w6*Sc+t] = bnyv; sRB[w6*Sc+t]  = rbv;

        // packed face coefficients for output rows (rr 2..SR+1)
        if (rr >= 2 && rr <= SR+1) {
            float c = sC[rr*Sc + t];
            float cfx = 0.f, cfy = 0.f;
            if (i < Sc-1) { float cn = sC[(rr+1)*Sc+t]; cfx = (2.f*c*cn / (c + cn + EPSF)) * INVH2; }
            if (t < Sc-1) { float ce = sC[rr*Sc+t+1];   cfy = (2.f*c*ce / (c + ce + EPSF)) * INVH2; }
            g_cf[off + (size_t)i*Sc + t] = make_float2(cfx, cfy);
        }
    }
    __syncthreads();

    // ---- rhs for rows r0 .. r0+SR-1 ----
#pragma unroll
    for (int k = 0; k < SR; k++) {
        int i = r0 + k;
        int w6 = k + 1;   // tile row of cell i in 6-row tiles
        int w8 = k + 2;   // tile row of cell i in 8-row tiles
        float rhs = 0.f;
        if (i > 0 && i < Sc-1 && t > 0 && t < Sc-1) {
            // fluxX between rows (a, a+1), same column t
            auto fluxX = [&](int a8, int a6) {
                float ca = sC[a8*Sc+t], cb = sC[(a8+1)*Sc+t];
                float cxf = 2.f*ca*cb / (ca + cb + EPSF);
                float gux = (sU[(a8+1)*Sc+t] - sU[a8*Sc+t]) * INVH;
                float lgx = (sLap[(a6+1)*Sc+t] - sLap[a6*Sc+t]) * INVH;
                return 0.5f*(sBB[a6*Sc+t]+sBB[(a6+1)*Sc+t]) * HH * cxf * lgx
                     + 0.5f*(sRho[a6*Sc+t]+sRho[(a6+1)*Sc+t]) * (0.5f*(sPP[a6*Sc+t]+sPP[(a6+1)*Sc+t])) * cxf * gux
                     + 0.5f*(sRB[a6*Sc+t]+sRB[(a6+1)*Sc+t]) * (0.5f*(sBNX[a6*Sc+t]+sBNX[(a6+1)*Sc+t])) * cxf * gux;
            };
            // fluxY between columns (j, j+1), row w8/w6
            auto fluxY = [&](int j) {
                float ca = sC[w8*Sc+j], cb = sC[w8*Sc+j+1];
                float cyf = 2.f*ca*cb / (ca + cb + EPSF);
                float guy = (sU[w8*Sc+j+1] - sU[w8*Sc+j]) * INVH;
                float lgy = (sLap[w6*Sc+j+1] - sLap[w6*Sc+j]) * INVH;
                return 0.5f*(sBB[w6*Sc+j]+sBB[w6*Sc+j+1]) * HH * cyf * lgy
                     + 0.5f*(sRho[w6*Sc+j]+sRho[w6*Sc+j+1]) * (0.5f*(sQQ[w6*Sc+j]+sQQ[w6*Sc+j+1])) * cyf * guy
                     + 0.5f*(sRB[w6*Sc+j]+sRB[w6*Sc+j+1]) * (0.5f*(sBNY[w6*Sc+j]+sBNY[w6*Sc+j+1])) * cyf * guy;
            };
            float fxN = fluxX(w8, w6);
            float fxS = fluxX(w8-1, w6-1);
            float fyE = fluxY(t);
            float fyW = fluxY(t-1);
            rhs = (fxN - fxS) * INVH + (fyE - fyW) * INVH;
        }
        g_r[off + (size_t)i*Sc + t] = rhs;
    }
}

// =====================================================================
// one barrier: deterministic reduction of two dots + fence
// =====================================================================
__device__ __forceinline__ float2 sync_reduce2(float va, float vb, float* sRed,
                                               int b, int rblk, unsigned ev) {
#pragma unroll
    for (int o = 16; o > 0; o >>= 1) {
        va += __shfl_down_sync(0xffffffffu, va, o);
        vb += __shfl_down_sync(0xffffffffu, vb, o);
    }
    if ((threadIdx.x & 31) == 0) {
        sRed[2*(threadIdx.x >> 5)]   = va;
        sRed[2*(threadIdx.x >> 5)+1] = vb;
    }
    __syncthreads();
    if (threadIdx.x == 0) {
        float sa = 0.f, sb = 0.f;
#pragma unroll
        for (int w = 0; w < 16; w++) { sa += sRed[2*w]; sb += sRed[2*w+1]; }
        g_part[b*BPB + rblk] = make_float2(sa, sb);
        unsigned old;
        asm volatile("atom.acq_rel.gpu.global.add.u32 %0, [%1], %2;"
                     : "=r"(old) : "l"(&g_cnt[b]), "r"(1u) : "memory");
        if (old == ev*BPB - 1u) {
            const float2* pp = &g_part[b*BPB];
            float ga = 0.f, gb2 = 0.f;
#pragma unroll
            for (int i = 0; i < BPB; i++) { float2 v = pp[i]; ga += v.x; gb2 += v.y; }
            unsigned long long pkA = ((unsigned long long)ev << 32) |
                                     (unsigned long long)__float_as_uint(ga);
            unsigned long long pkB = ((unsigned long long)ev << 32) |
                                     (unsigned long long)__float_as_uint(gb2);
            asm volatile("st.release.gpu.global.b64 [%0], %1;" :: "l"(&g_pubA[b]), "l"(pkA) : "memory");
            asm volatile("st.release.gpu.global.b64 [%0], %1;" :: "l"(&g_pubB[b]), "l"(pkB) : "memory");
            sRed[0] = ga; sRed[1] = gb2;
        } else {
            unsigned long long pk;
            do {
                asm volatile("ld.acquire.gpu.global.b64 %0, [%1];"
                             : "=l"(pk) : "l"(&g_pubB[b]) : "memory");
            } while ((unsigned)(pk >> 32) != ev);
            sRed[1] = __uint_as_float((unsigned)pk);
            do {
                asm volatile("ld.acquire.gpu.global.b64 %0, [%1];"
                             : "=l"(pk) : "l"(&g_pubA[b]) : "memory");
            } while ((unsigned)(pk >> 32) != ev);
            sRed[0] = __uint_as_float((unsigned)pk);
        }
    }
    __syncthreads();
    float2 r = make_float2(sRed[0], sRed[1]);
    __syncthreads();
    return r;
}

#define SMEM_FLOATS (3*RMAX*PT + 64)
#define SMEM_BYTES (SMEM_FLOATS * 4)

// =====================================================================
// Persistent pipelined-CG (R5 structure: two passes, one barrier/iter)
// =====================================================================
__global__ void __launch_bounds__(PT, 2)
cg_kernel(const float* __restrict__ u, float* __restrict__ out) {
    extern __shared__ float sm[];
    float* sW   = sm;
    float* sS   = sm + RMAX*PT;
    float* sZ   = sS + RMAX*PT;
    float* sRed = sZ + RMAX*PT;

    const int t = threadIdx.x;
    const int blk = blockIdx.x;
    const int b = blk / BPB;
    const int rblk = blk - b*BPB;
    const int start = (rblk < 31) ? rblk*14 : 434 + (rblk-31)*13;
    const int nr = (rblk < 31) ? 14 : 13;
    const size_t off = (size_t)b * Nc;
    const size_t gb = off + (size_t)start * Sc + t;
    const float2* __restrict__ CF = g_cf + off;
    unsigned ev = 0;

    const bool interiorT = (t > 0 && t < Sc-1);
    const int tcy = (t > 0) ? t-1 : 0;
    float r[RMAX], p[RMAX], x[RMAX];

    // ---- init: load r, stage in sS, w0 = A r0, dots ----
#pragma unroll
    for (int k = 0; k < RMAX; k++) {
        bool act = (k < nr);
        float rv = act ? g_r[gb + k*Sc] : 0.f;
        r[k] = rv;
        sS[k*PT + t] = rv;
        p[k] = 0.f;
        x[k] = 0.f;
    }
    __syncthreads();

    float accA = 0.f, accB = 0.f;
    {
        float rHT = (rblk > 0)     ? g_r[gb - Sc]     : 0.f;
        float rHB = (rblk < BPB-1) ? g_r[gb + nr*Sc]  : 0.f;
        float cxp = CF[(size_t)(start > 0 ? start-1 : 0)*Sc + t].x;
#pragma unroll
        for (int k = 0; k < RMAX; k++) {
            bool act = (k < nr);
            int i = start + k;
            int ii = act ? i : Sc-1;
            float2 cf = CF[(size_t)ii*Sc + t];
            float cye = cf.y;
            float cyw = __shfl_up_sync(0xffffffffu, cye, 1);
            if ((t & 31) == 0) cyw = CF[(size_t)ii*Sc + tcy].y;
            float w = 0.f;
            if (act && i > 0 && i < Sc-1 && interiorT) {
                float rc = r[k];
                float ru = (k == nr-1) ? rHB : sS[(k+1)*PT + t];
                float rd = (k == 0)    ? rHT : sS[(k-1)*PT + t];
                float re = sS[k*PT + t + 1];
                float rw_ = sS[k*PT + t - 1];
                w = cf.x*(rc-ru) + cxp*(rc-rd) + cye*(rc-re) + cyw*(rc-rw_);
            }
            sW[k*PT + t] = w;
            accA += r[k]*r[k];
            accB += w*r[k];
            if (act && (k == 0 || k == nr-1)) g_w[gb + k*Sc] = w;
            cxp = cf.x;
        }
    }
    __syncthreads();
#pragma unroll
    for (int k = 0; k < RMAX; k++) { sS[k*PT + t] = 0.f; sZ[k*PT + t] = 0.f; }

    float gamma_old = 1.f, alpha_old = 1.f;

    for (int it = 0; it < ITERS; it++) {
        ev++;
        float2 gd = sync_reduce2(accA, accB, sRed, b, rblk, ev);
        float G = gd.x, D = gd.y;
        float beta, alpha;
        if (it == 0) {
            beta = 0.f;
            alpha = G / fmaxf(D, EPSF);
        } else {
            beta = G / fmaxf(gamma_old, EPSF);
            float den = D - beta * G / alpha_old;
            alpha = G / fmaxf(den, EPSF);
        }

        if (it == ITERS-1) {
#pragma unroll
            for (int k = 0; k < RMAX; k++) {
                float pv = r[k] + beta * p[k];
                x[k] += alpha * pv;
            }
            break;
        }

        // ---- pass 1: q = A w ; z = q + beta*z ----
        {
            float wHT = (rblk > 0)     ? g_w[gb - Sc]     : 0.f;
            float wHB = (rblk < BPB-1) ? g_w[gb + nr*Sc]  : 0.f;
            float cxp = CF[(size_t)(start > 0 ? start-1 : 0)*Sc + t].x;
#pragma unroll
            for (int k = 0; k < RMAX; k++) {
                bool act = (k < nr);
                int i = start + k;
                int ii = act ? i : Sc-1;
                float2 cf = CF[(size_t)ii*Sc + t];
                float cye = cf.y;
                float cyw = __shfl_up_sync(0xffffffffu, cye, 1);
                if ((t & 31) == 0) cyw = CF[(size_t)ii*Sc + tcy].y;
                float q = 0.f;
                if (act && i > 0 && i < Sc-1 && interiorT) {
                    float wc = sW[k*PT + t];
                    float wu = (k == nr-1) ? wHB : sW[(k+1)*PT + t];
                    float wd = (k == 0)    ? wHT : sW[(k-1)*PT + t];
                    float we = sW[k*PT + t + 1];
                    float ww = sW[k*PT + t - 1];
                    q = cf.x*(wc-wu) + cxp*(wc-wd) + cye*(wc-we) + cyw*(wc-ww);
                }
                sZ[k*PT + t] = q + beta * sZ[k*PT + t];
                cxp = cf.x;
            }
        }
        __syncthreads();

        // ---- pass 2: recurrences + next dots + edge-w exchange ----
        accA = 0.f; accB = 0.f;
#pragma unroll
        for (int k = 0; k < RMAX; k++) {
            bool act = (k < nr);
            float wc = sW[k*PT + t];
            float sv = wc + beta * sS[k*PT + t];
            sS[k*PT + t] = sv;
            float pv = r[k] + beta * p[k];
            p[k] = pv;
            x[k] += alpha * pv;
            float rv = r[k] - alpha * sv;
            r[k] = rv;
            float wv = wc - alpha * sZ[k*PT + t];
            sW[k*PT + t] = wv;
            accA += rv * rv;
            accB += wv * rv;
            if (act && (k == 0 || k == nr-1)) g_w[gb + k*Sc] = wv;
        }
        gamma_old = G;
        alpha_old = alpha;
    }

    // ---- output: out = zb(u + x) ----
#pragma unroll
    for (int k = 0; k < RMAX; k++) {
        if (k >= nr) continue;
        int i = start + k;
        size_t gi = gb + k*Sc;
        float v = 0.f;
        if (i > 0 && i < Sc-1 && interiorT) v = u[gi] + x[k];
        out[gi] = v;
    }
}

extern "C" void kernel_launch(void* const* d_in, const int* in_sizes, int n_in,
                              void* d_out, int out_size) {
    const float* coeff = (const float*)d_in[0];
    const float* u     = (const float*)d_in[1];
    const float* beta  = (const float*)d_in[2];
    float* out = (float*)d_out;

    cudaFuncSetAttribute(sf_kernel, cudaFuncAttributeMaxDynamicSharedMemorySize, SF_BYTES);
    cudaFuncSetAttribute(cg_kernel, cudaFuncAttributeMaxDynamicSharedMemorySize, SMEM_BYTES);

    dim3 g1(Sc/SR, Bc);
    sf_kernel<<<g1, 512, SF_BYTES>>>(coeff, u, beta);
    cg_kernel<<<PB, PT, SMEM_BYTES>>>(u, out);
}

// round 16
// speedup vs baseline: 1.1349x; 1.0519x over previous
#include <cuda_runtime.h>
#include <math.h>

#define Bc 8
#define Sc 512
#define Nc (Sc*Sc)
#define ITERS 20
#define EPSF 1e-6f
#define INVH 511.0f
#define HF (1.0f/511.0f)
#define HH (HF*HF)
#define INVH2 (511.0f*511.0f)
#define GAMMA_F 10.0f
#define THRESH_F 0.5f

#define PT 512
#define BPB 37
#define PB (Bc*BPB)
#define RMAX 14

// ---- scratch ----
__device__ float2 g_cf[Bc*Nc];          // packed (cx_north, cy_east) * 1/h^2
__device__ float g_r[Bc*Nc];            // edge rows only
__device__ float g_w[Bc*Nc];            // edge rows only
__device__ float2 g_part[Bc*BPB];
__device__ unsigned g_cnt[Bc];
__device__ unsigned long long g_pubA[Bc];
__device__ unsigned long long g_pubB[Bc];

__global__ void zc_kernel() {
    if (threadIdx.x < Bc) {
        g_cnt[threadIdx.x] = 0u;
        g_pubA[threadIdx.x] = 0ull;
        g_pubB[threadIdx.x] = 0ull;
    }
}

// =====================================================================
// one barrier: deterministic reduction of two dots + fence
// =====================================================================
__device__ __forceinline__ float2 sync_reduce2(float va, float vb, float* sRed,
                                               int b, int rblk, unsigned ev) {
#pragma unroll
    for (int o = 16; o > 0; o >>= 1) {
        va += __shfl_down_sync(0xffffffffu, va, o);
        vb += __shfl_down_sync(0xffffffffu, vb, o);
    }
    if ((threadIdx.x & 31) == 0) {
        sRed[2*(threadIdx.x >> 5)]   = va;
        sRed[2*(threadIdx.x >> 5)+1] = vb;
    }
    __syncthreads();
    if (threadIdx.x == 0) {
        float sa = 0.f, sb = 0.f;
#pragma unroll
        for (int w = 0; w < 16; w++) { sa += sRed[2*w]; sb += sRed[2*w+1]; }
        g_part[b*BPB + rblk] = make_float2(sa, sb);
        unsigned old;
        asm volatile("atom.acq_rel.gpu.global.add.u32 %0, [%1], %2;"
                     : "=r"(old) : "l"(&g_cnt[b]), "r"(1u) : "memory");
        if (old == ev*BPB - 1u) {
            const float2* pp = &g_part[b*BPB];
            float ga = 0.f, gb2 = 0.f;
#pragma unroll
            for (int i = 0; i < BPB; i++) { float2 v = pp[i]; ga += v.x; gb2 += v.y; }
            unsigned long long pkA = ((unsigned long long)ev << 32) |
                                     (unsigned long long)__float_as_uint(ga);
            unsigned long long pkB = ((unsigned long long)ev << 32) |
                                     (unsigned long long)__float_as_uint(gb2);
            asm volatile("st.release.gpu.global.b64 [%0], %1;" :: "l"(&g_pubA[b]), "l"(pkA) : "memory");
            asm volatile("st.release.gpu.global.b64 [%0], %1;" :: "l"(&g_pubB[b]), "l"(pkB) : "memory");
            sRed[0] = ga; sRed[1] = gb2;
        } else {
            unsigned long long pk;
            do {
                asm volatile("ld.acquire.gpu.global.b64 %0, [%1];"
                             : "=l"(pk) : "l"(&g_pubB[b]) : "memory");
            } while ((unsigned)(pk >> 32) != ev);
            sRed[1] = __uint_as_float((unsigned)pk);
            do {
                asm volatile("ld.acquire.gpu.global.b64 %0, [%1];"
                             : "=l"(pk) : "l"(&g_pubA[b]) : "memory");
            } while ((unsigned)(pk >> 32) != ev);
            sRed[0] = __uint_as_float((unsigned)pk);
        }
    }
    __syncthreads();
    float2 r = make_float2(sRed[0], sRed[1]);
    __syncthreads();
    return r;
}

// smem: phase0 needs (18+18+3+12)*Sc = 26112 floats; loop needs 3*RMAX*PT+64 = 21568
#define SMEM_FLOATS 26112
#define SMEM_BYTES (SMEM_FLOATS * 4)

// =====================================================================
// Persistent kernel: phase-0 setup (rhs + face coeffs in-block) then
// pipelined CG (R5 loop, 1 barrier/iter)
// =====================================================================
__global__ void __launch_bounds__(PT, 2)
cg_kernel(const float* __restrict__ coeff, const float* __restrict__ u,
          const float* __restrict__ beta4, float* __restrict__ out) {
    extern __shared__ float sm[];

    const int t = threadIdx.x;
    const int blk = blockIdx.x;
    const int b = blk / BPB;
    const int rblk = blk - b*BPB;
    const int start = (rblk < 31) ? rblk*14 : 434 + (rblk-31)*13;
    const int nr = (rblk < 31) ? 14 : 13;
    const size_t off = (size_t)b * Nc;
    const size_t gb = off + (size_t)start * Sc + t;
    const float4* __restrict__ B4 = (const float4*)beta4 + off;

    float r[RMAX], p[RMAX], x[RMAX];

    // ================= PHASE 0: in-block setup =================
    {
        float* sC = sm;               // 18 rows: start-2 .. start+15
        float* sU = sm + 18*Sc;       // 18 rows
        float* sL = sm + 36*Sc;       // 3-row ring of log(coeff)
        float* sD = sm + 39*Sc;       // 2 rings x 6 fields: 0=lap 1=rho 2=Q 3=BB 4=BNY 5=RB

#pragma unroll
        for (int rr = 0; rr < 18; rr++) {
            int i = start - 2 + rr;
            bool in = (i >= 0 && i < Sc);
            sC[rr*Sc + t] = in ? coeff[off + (size_t)i*Sc + t] : 1.f;
            sU[rr*Sc + t] = in ? u[off + (size_t)i*Sc + t] : 0.f;
        }
        __syncthreads();
        // prime L for rows start-2 (slot 0), start-1 (slot 1)
        sL[0*Sc + t] = logf(fmaxf(sC[0*Sc + t], EPSF));
        sL[1*Sc + t] = logf(fmaxf(sC[1*Sc + t], EPSF));

        float accA = 0.f;
        float prevP = 0.f, prevBNX = 0.f, curP = 0.f, curBNX = 0.f;
        float fxS = 0.f;

#pragma unroll
        for (int s = 0; s < 16; s++) {      // derived rows i = start-1 .. start+14
            int i = start - 1 + s;
            int rr = s + 1;                  // sC/sU row of i
            // L row i+1 -> slot (s+2)%3
            sL[((s+2)%3)*Sc + t] = logf(fmaxf(sC[(rr+1)*Sc + t], EPSF));
            __syncthreads();

            // derived row i
            int d = s & 1;
            prevP = curP; prevBNX = curBNX;
            float lap = 0.f, rho = 0.f, Qv = 0.f, BBv = 0.f, BNYv = 0.f, RBv = 0.f;
            curP = 0.f; curBNX = 0.f;
            bool vi = (i >= 0 && i < Sc);
            if (vi) {
                if (i > 0 && i < Sc-1 && t > 0 && t < Sc-1) {
                    float uc = sU[rr*Sc + t];
                    lap = ((sU[(rr+1)*Sc+t]-uc)*INVH - (uc-sU[(rr-1)*Sc+t])*INVH)*INVH
                        + ((sU[rr*Sc+t+1]-uc)*INVH - (uc-sU[rr*Sc+t-1])*INVH)*INVH;
                }
                int sl_m = s % 3, sl_c = (s+1) % 3, sl_p = (s+2) % 3;
                float lc = sL[sl_c*Sc + t];
                float glx, gly;
                if (i == 0)          glx = (sL[sl_p*Sc+t] - lc) * INVH;
                else if (i == Sc-1)  glx = (lc - sL[sl_m*Sc+t]) * INVH;
                else                 glx = (sL[sl_p*Sc+t] - sL[sl_m*Sc+t]) * (0.5f*INVH);
                if (t == 0)          gly = (sL[sl_c*Sc+t+1] - lc) * INVH;
                else if (t == Sc-1)  gly = (lc - sL[sl_c*Sc+t-1]) * INVH;
                else                 gly = (sL[sl_c*Sc+t+1] - sL[sl_c*Sc+t-1]) * (0.5f*INVH);

                float eta = sqrtf(glx*glx + gly*gly + EPSF);
                rho = 1.f / (1.f + expf(-GAMMA_F * (eta - THRESH_F)));
                float nhx = glx / eta, nhy = gly / eta;

                float4 bv = B4[(size_t)i*Sc + t];
                curP = bv.y*nhx - bv.z*nhy;
                Qv   = bv.y*nhy + bv.z*nhx;
                BBv  = bv.x;

                float bnx, bny, dd;
                if (i + t != 511) {
                    int m0 = i, m1 = 511-i, m2 = t, m3 = 511-t;
                    int best = m0, kk = 0;
                    if (m1 < best) { best = m1; kk = 1; }
                    if (m2 < best) { best = m2; kk = 2; }
                    if (m3 < best) { best = m3; kk = 3; }
                    bnx = (kk == 0) ? -1.f : ((kk == 1) ? 1.f : 0.f);
                    bny = (kk == 2) ? -1.f : ((kk == 3) ? 1.f : 0.f);
                    dd = (float)((double)best * (1.0/511.0));
                } else {
                    double dl = 1.0 / 511.0;
                    double xx = (i == Sc-1) ? 1.0 : (double)i * dl;
                    double yy = (t == Sc-1) ? 1.0 : (double)t * dl;
                    double a0 = xx, a1 = 1.0 - xx, a2 = yy, a3 = 1.0 - yy;
                    double best = a0; int kk = 0;
                    if (a1 < best) { best = a1; kk = 1; }
                    if (a2 < best) { best = a2; kk = 2; }
                    if (a3 < best) { best = a3; kk = 3; }
                    bnx = (kk == 0) ? -1.f : ((kk == 1) ? 1.f : 0.f);
                    bny = (kk == 2) ? -1.f : ((kk == 3) ? 1.f : 0.f);
                    dd = (float)best;
                }
                curBNX = bv.w * bnx;
                BNYv   = bv.w * bny;
                RBv = expf(-(dd*dd) / (0.15f*0.15f));

                // face coefficients for own rows -> global (for CG loop)
                if (i >= start && i < start + nr) {
                    float c = sC[rr*Sc + t];
                    float cfx = 0.f, cfy = 0.f;
                    if (i < Sc-1) { float cn = sC[(rr+1)*Sc+t]; cfx = (2.f*c*cn/(c+cn+EPSF))*INVH2; }
                    if (t < Sc-1) { float ce = sC[rr*Sc+t+1];   cfy = (2.f*c*ce/(c+ce+EPSF))*INVH2; }
                    g_cf[off + (size_t)i*Sc + t] = make_float2(cfx, cfy);
                }
            }
            sD[(d*6+0)*Sc+t] = lap;  sD[(d*6+1)*Sc+t] = rho;
            sD[(d*6+2)*Sc+t] = Qv;   sD[(d*6+3)*Sc+t] = BBv;
            sD[(d*6+4)*Sc+t] = BNYv; sD[(d*6+5)*Sc+t] = RBv;
            __syncthreads();

            // flux + rhs for row i-1
            if (s >= 1) {
                int dp = d ^ 1;
                int ra = rr - 1;
                float fxN;
                {
                    float ca = sC[ra*Sc+t], cb = sC[rr*Sc+t];
                    float cxf = 2.f*ca*cb / (ca + cb + EPSF);
                    float gux = (sU[rr*Sc+t] - sU[ra*Sc+t]) * INVH;
                    float lgx = (sD[(d*6+0)*Sc+t] - sD[(dp*6+0)*Sc+t]) * INVH;
                    fxN = 0.5f*(sD[(dp*6+3)*Sc+t]+sD[(d*6+3)*Sc+t]) * HH * cxf * lgx
                        + 0.5f*(sD[(dp*6+1)*Sc+t]+sD[(d*6+1)*Sc+t]) * (0.5f*(prevP+curP)) * cxf * gux
                        + 0.5f*(sD[(dp*6+5)*Sc+t]+sD[(d*6+5)*Sc+t]) * (0.5f*(prevBNX+curBNX)) * cxf * gux;
                }
                int iw = i - 1;
                int k = s - 2;                     // compile-time per unroll step
                if (k >= 0 && k < nr) {
                    float rhs = 0.f;
                    if (iw > 0 && iw < Sc-1 && t > 0 && t < Sc-1) {
                        auto fy = [&](int j) {
                            float ca = sC[ra*Sc+j], cb = sC[ra*Sc+j+1];
                            float cyf = 2.f*ca*cb / (ca + cb + EPSF);
                            float guy = (sU[ra*Sc+j+1] - sU[ra*Sc+j]) * INVH;
                            float lgy = (sD[(dp*6+0)*Sc+j+1] - sD[(dp*6+0)*Sc+j]) * INVH;
                            return 0.5f*(sD[(dp*6+3)*Sc+j]+sD[(dp*6+3)*Sc+j+1]) * HH * cyf * lgy
                                 + 0.5f*(sD[(dp*6+1)*Sc+j]+sD[(dp*6+1)*Sc+j+1]) * (0.5f*(sD[(dp*6+2)*Sc+j]+sD[(dp*6+2)*Sc+j+1])) * cyf * guy
                                 + 0.5f*(sD[(dp*6+5)*Sc+j]+sD[(dp*6+5)*Sc+j+1]) * (0.5f*(sD[(dp*6+4)*Sc+j]+sD[(dp*6+4)*Sc+j+1])) * cyf * guy;
                        };
                        float fyE = fy(t), fyW = fy(t-1);
                        rhs = (fxN - fxS) * INVH + (fyE - fyW) * INVH;
                    }
                    if (k < RMAX) {
                        r[k] = rhs;
                        accA += rhs * rhs;
                        if (k == 0 || k == nr-1) g_r[gb + k*Sc] = rhs;
                    }
                }
                fxS = fxN;
            }
        }
        __syncthreads();   // all phase-0 smem reads done before loop-region reuse

        // stash accA in r-unused slot trick not needed; carry via register:
        // (accA flows into ev1 below — keep in scope)
        // ================= transition to CG loop =================
        float* sW   = sm;
        float* sS   = sm + RMAX*PT;
        float* sZ   = sm + 2*RMAX*PT;
        float* sRed = sm + 3*RMAX*PT;
        unsigned ev = 0;

        const bool interiorT = (t > 0 && t < Sc-1);
        const int tcy = (t > 0) ? t-1 : 0;
        const float2* __restrict__ CF = g_cf + off;

#pragma unroll
        for (int k = 0; k < RMAX; k++) {
            if (k >= nr) r[k] = 0.f;
            p[k] = 0.f; x[k] = 0.f;
        }

        ev = 1;
        float G = sync_reduce2(accA, accA, sRed, b, rblk, ev).x;   // gamma0; fences g_r/g_cf

        // stage r for horizontal stencil access
#pragma unroll
        for (int k = 0; k < RMAX; k++) sS[k*PT + t] = r[k];
        __syncthreads();

        // w0 = A r0
        float accB = 0.f;
        {
            float rHT = (rblk > 0)     ? g_r[gb - Sc]     : 0.f;
            float rHB = (rblk < BPB-1) ? g_r[gb + nr*Sc]  : 0.f;
            float cxp = CF[(size_t)(start > 0 ? start-1 : 0)*Sc + t].x;
#pragma unroll
            for (int k = 0; k < RMAX; k++) {
                bool act = (k < nr);
                int i = start + k;
                int ii = act ? i : Sc-1;
                float2 cf = CF[(size_t)ii*Sc + t];
                float cye = cf.y;
                float cyw = __shfl_up_sync(0xffffffffu, cye, 1);
                if ((t & 31) == 0) cyw = CF[(size_t)ii*Sc + tcy].y;
                float w = 0.f;
                if (act && i > 0 && i < Sc-1 && interiorT) {
                    float rc = r[k];
                    float ru = (k == nr-1) ? rHB : sS[(k+1)*PT + t];
                    float rd = (k == 0)    ? rHT : sS[(k-1)*PT + t];
                    float re = sS[k*PT + t + 1];
                    float rw_ = sS[k*PT + t - 1];
                    w = cf.x*(rc-ru) + cxp*(rc-rd) + cye*(rc-re) + cyw*(rc-rw_);
                }
                sW[k*PT + t] = w;
                accB += w * r[k];
                if (act && (k == 0 || k == nr-1)) g_w[gb + k*Sc] = w;
                cxp = cf.x;
            }
        }
        __syncthreads();
#pragma unroll
        for (int k = 0; k < RMAX; k++) { sS[k*PT + t] = 0.f; sZ[k*PT + t] = 0.f; }

        ev = 2;
        float D = sync_reduce2(accB, accB, sRed, b, rblk, ev).y;   // delta0; fences g_w

        float gamma_prev = 1.f, alpha_prev = 1.f;
        float accAn = 0.f, accBn = 0.f;

        for (int it = 0; it < ITERS; it++) {
            float beta, alpha;
            if (it == 0) {
                beta = 0.f;
                alpha = G / fmaxf(D, EPSF);
            } else {
                beta = G / fmaxf(gamma_prev, EPSF);
                float den = D - beta * G / alpha_prev;
                alpha = G / fmaxf(den, EPSF);
            }

            if (it == ITERS-1) {
#pragma unroll
                for (int k = 0; k < RMAX; k++) {
                    float pv = r[k] + beta * p[k];
                    x[k] += alpha * pv;
                }
                break;
            }

            // ---- pass 1: q = A w ; z = q + beta*z ----
            {
                float wHT = (rblk > 0)     ? g_w[gb - Sc]     : 0.f;
                float wHB = (rblk < BPB-1) ? g_w[gb + nr*Sc]  : 0.f;
                float cxp = CF[(size_t)(start > 0 ? start-1 : 0)*Sc + t].x;
#pragma unroll
                for (int k = 0; k < RMAX; k++) {
                    bool act = (k < nr);
                    int i = start + k;
                    int ii = act ? i : Sc-1;
                    float2 cf = CF[(size_t)ii*Sc + t];
                    float cye = cf.y;
                    float cyw = __shfl_up_sync(0xffffffffu, cye, 1);
                    if ((t & 31) == 0) cyw = CF[(size_t)ii*Sc + tcy].y;
                    float q = 0.f;
                    if (act && i > 0 && i < Sc-1 && interiorT) {
                        float wc = sW[k*PT + t];
                        float wu = (k == nr-1) ? wHB : sW[(k+1)*PT + t];
                        float wd = (k == 0)    ? wHT : sW[(k-1)*PT + t];
                        float we = sW[k*PT + t + 1];
                        float ww = sW[k*PT + t - 1];
                        q = cf.x*(wc-wu) + cxp*(wc-wd) + cye*(wc-we) + cyw*(wc-ww);
                    }
                    sZ[k*PT + t] = q + beta * sZ[k*PT + t];
                    cxp = cf.x;
                }
            }
            __syncthreads();

            // ---- pass 2: recurrences + next dots + edge-w exchange ----
            accAn = 0.f; accBn = 0.f;
#pragma unroll
            for (int k = 0; k < RMAX; k++) {
                bool act = (k < nr);
                float wc = sW[k*PT + t];
                float sv = wc + beta * sS[k*PT + t];
                sS[k*PT + t] = sv;
                float pv = r[k] + beta * p[k];
                p[k] = pv;
                x[k] += alpha * pv;
                float rv = r[k] - alpha * sv;
                r[k] = rv;
                float wv = wc - alpha * sZ[k*PT + t];
                sW[k*PT + t] = wv;
                accAn += rv * rv;
                accBn += wv * rv;
                if (act && (k == 0 || k == nr-1)) g_w[gb + k*Sc] = wv;
            }
            gamma_prev = G;
            alpha_prev = alpha;
            ev++;
            float2 gd = sync_reduce2(accAn, accBn, sRed, b, rblk, ev);
            G = gd.x; D = gd.y;
        }
    }

    // ---- output: out = zb(u + x) ----
    const bool interiorT2 = (t > 0 && t < Sc-1);
#pragma unroll
    for (int k = 0; k < RMAX; k++) {
        if (k >= nr) continue;
        int i = start + k;
        size_t gi = gb + k*Sc;
        float v = 0.f;
        if (i > 0 && i < Sc-1 && interiorT2) v = u[gi] + x[k];
        out[gi] = v;
    }
}

extern "C" void kernel_launch(void* const* d_in, const int* in_sizes, int n_in,
                              void* d_out, int out_size) {
    const float* coeff = (const float*)d_in[0];
    const float* u     = (const float*)d_in[1];
    const float* beta  = (const float*)d_in[2];
    float* out = (float*)d_out;

    cudaFuncSetAttribute(cg_kernel, cudaFuncAttributeMaxDynamicSharedMemorySize, SMEM_BYTES);

    zc_kernel<<<1, 32>>>();
    cg_kernel<<<PB, PT, SMEM_BYTES>>>(coeff, u, beta, out);
}

// round 17
// speedup vs baseline: 1.1475x; 1.0111x over previous
#include <cuda_runtime.h>
#include <math.h>

#define Bc 8
#define Sc 512
#define Nc (Sc*Sc)
#define ITERS 20
#define EPSF 1e-6f
#define INVH 511.0f
#define HF (1.0f/511.0f)
#define HH (HF*HF)
#define INVH2 (511.0f*511.0f)
#define GAMMA_F 10.0f
#define THRESH_F 0.5f

#define PT 512
#define BPB 37
#define PB (Bc*BPB)
#define RMAX 14

// ---- scratch ----
__device__ float2 g_cf[Bc*Nc];          // packed (cx_north, cy_east) * 1/h^2
__device__ float g_r[Bc*Nc];            // edge rows only
__device__ float g_w[Bc*Nc];            // edge rows only
__device__ float2 g_part[Bc*BPB];
__device__ unsigned g_cnt[Bc];
__device__ unsigned long long g_pubA[Bc];
__device__ unsigned long long g_pubB[Bc];

__global__ void zc_kernel() {
    if (threadIdx.x < Bc) {
        g_cnt[threadIdx.x] = 0u;
        g_pubA[threadIdx.x] = 0ull;
        g_pubB[threadIdx.x] = 0ull;
    }
}

// =====================================================================
// one barrier: deterministic reduction of two dots + fence
// =====================================================================
__device__ __forceinline__ float2 sync_reduce2(float va, float vb, float* sRed,
                                               int b, int rblk, unsigned ev) {
#pragma unroll
    for (int o = 16; o > 0; o >>= 1) {
        va += __shfl_down_sync(0xffffffffu, va, o);
        vb += __shfl_down_sync(0xffffffffu, vb, o);
    }
    if ((threadIdx.x & 31) == 0) {
        sRed[2*(threadIdx.x >> 5)]   = va;
        sRed[2*(threadIdx.x >> 5)+1] = vb;
    }
    __syncthreads();
    if (threadIdx.x == 0) {
        float sa = 0.f, sb = 0.f;
#pragma unroll
        for (int w = 0; w < 16; w++) { sa += sRed[2*w]; sb += sRed[2*w+1]; }
        g_part[b*BPB + rblk] = make_float2(sa, sb);
        unsigned old;
        asm volatile("atom.acq_rel.gpu.global.add.u32 %0, [%1], %2;"
                     : "=r"(old) : "l"(&g_cnt[b]), "r"(1u) : "memory");
        if (old == ev*BPB - 1u) {
            const float2* pp = &g_part[b*BPB];
            float ga = 0.f, gb2 = 0.f;
#pragma unroll
            for (int i = 0; i < BPB; i++) { float2 v = pp[i]; ga += v.x; gb2 += v.y; }
            unsigned long long pkA = ((unsigned long long)ev << 32) |
                                     (unsigned long long)__float_as_uint(ga);
            unsigned long long pkB = ((unsigned long long)ev << 32) |
                                     (unsigned long long)__float_as_uint(gb2);
            asm volatile("st.release.gpu.global.b64 [%0], %1;" :: "l"(&g_pubA[b]), "l"(pkA) : "memory");
            asm volatile("st.release.gpu.global.b64 [%0], %1;" :: "l"(&g_pubB[b]), "l"(pkB) : "memory");
            sRed[0] = ga; sRed[1] = gb2;
        } else {
            unsigned long long pk;
            do {
                asm volatile("ld.acquire.gpu.global.b64 %0, [%1];"
                             : "=l"(pk) : "l"(&g_pubB[b]) : "memory");
            } while ((unsigned)(pk >> 32) != ev);
            sRed[1] = __uint_as_float((unsigned)pk);
            do {
                asm volatile("ld.acquire.gpu.global.b64 %0, [%1];"
                             : "=l"(pk) : "l"(&g_pubA[b]) : "memory");
            } while ((unsigned)(pk >> 32) != ev);
            sRed[0] = __uint_as_float((unsigned)pk);
        }
    }
    __syncthreads();
    float2 r = make_float2(sRed[0], sRed[1]);
    __syncthreads();
    return r;
}

// smem: phase0 needs (18+18+3+12)*Sc = 26112 floats; loop needs 3*RMAX*PT+64 = 21568
#define SMEM_FLOATS 26112
#define SMEM_BYTES (SMEM_FLOATS * 4)

// =====================================================================
// Persistent kernel: phase-0 setup (rhs + face coeffs in-block) then
// pipelined CG (R5 loop, 1 barrier/iter)
// =====================================================================
__global__ void __launch_bounds__(PT, 2)
cg_kernel(const float* __restrict__ coeff, const float* __restrict__ u,
          const float* __restrict__ beta4, float* __restrict__ out) {
    extern __shared__ float sm[];

    const int t = threadIdx.x;
    const int blk = blockIdx.x;
    const int b = blk / BPB;
    const int rblk = blk - b*BPB;
    const int start = (rblk < 31) ? rblk*14 : 434 + (rblk-31)*13;
    const int nr = (rblk < 31) ? 14 : 13;
    const size_t off = (size_t)b * Nc;
    const size_t gb = off + (size_t)start * Sc + t;
    const float4* __restrict__ B4 = (const float4*)beta4 + off;

    float r[RMAX], p[RMAX], x[RMAX];

    // ================= PHASE 0: in-block setup =================
    {
        float* sC = sm;               // 18 rows: start-2 .. start+15
        float* sU = sm + 18*Sc;       // 18 rows
        float* sL = sm + 36*Sc;       // 3-row ring of log(coeff)
        float* sD = sm + 39*Sc;       // 2 rings x 6 fields: 0=lap 1=rho 2=Q 3=BB 4=BNY 5=RB

#pragma unroll
        for (int rr = 0; rr < 18; rr++) {
            int i = start - 2 + rr;
            bool in = (i >= 0 && i < Sc);
            sC[rr*Sc + t] = in ? coeff[off + (size_t)i*Sc + t] : 1.f;
            sU[rr*Sc + t] = in ? u[off + (size_t)i*Sc + t] : 0.f;
        }
        __syncthreads();
        // prime L for rows start-2 (slot 0), start-1 (slot 1)
        sL[0*Sc + t] = logf(fmaxf(sC[0*Sc + t], EPSF));
        sL[1*Sc + t] = logf(fmaxf(sC[1*Sc + t], EPSF));

        float accA = 0.f;
        float prevP = 0.f, prevBNX = 0.f, curP = 0.f, curBNX = 0.f;
        float fxS = 0.f;

#pragma unroll
        for (int s = 0; s < 16; s++) {      // derived rows i = start-1 .. start+14
            int i = start - 1 + s;
            int rr = s + 1;                  // sC/sU row of i
            // L row i+1 -> slot (s+2)%3
            sL[((s+2)%3)*Sc + t] = logf(fmaxf(sC[(rr+1)*Sc + t], EPSF));
            __syncthreads();

            // derived row i
            int d = s & 1;
            prevP = curP; prevBNX = curBNX;
            float lap = 0.f, rho = 0.f, Qv = 0.f, BBv = 0.f, BNYv = 0.f, RBv = 0.f;
            curP = 0.f; curBNX = 0.f;
            bool vi = (i >= 0 && i < Sc);
            if (vi) {
                if (i > 0 && i < Sc-1 && t > 0 && t < Sc-1) {
                    float uc = sU[rr*Sc + t];
                    lap = ((sU[(rr+1)*Sc+t]-uc)*INVH - (uc-sU[(rr-1)*Sc+t])*INVH)*INVH
                        + ((sU[rr*Sc+t+1]-uc)*INVH - (uc-sU[rr*Sc+t-1])*INVH)*INVH;
                }
                int sl_m = s % 3, sl_c = (s+1) % 3, sl_p = (s+2) % 3;
                float lc = sL[sl_c*Sc + t];
                float glx, gly;
                if (i == 0)          glx = (sL[sl_p*Sc+t] - lc) * INVH;
                else if (i == Sc-1)  glx = (lc - sL[sl_m*Sc+t]) * INVH;
                else                 glx = (sL[sl_p*Sc+t] - sL[sl_m*Sc+t]) * (0.5f*INVH);
                if (t == 0)          gly = (sL[sl_c*Sc+t+1] - lc) * INVH;
                else if (t == Sc-1)  gly = (lc - sL[sl_c*Sc+t-1]) * INVH;
                else                 gly = (sL[sl_c*Sc+t+1] - sL[sl_c*Sc+t-1]) * (0.5f*INVH);

                float eta = sqrtf(glx*glx + gly*gly + EPSF);
                rho = 1.f / (1.f + expf(-GAMMA_F * (eta - THRESH_F)));
                float nhx = glx / eta, nhy = gly / eta;

                float4 bv = B4[(size_t)i*Sc + t];
                curP = bv.y*nhx - bv.z*nhy;
                Qv   = bv.y*nhy + bv.z*nhx;
                BBv  = bv.x;

                float bnx, bny, dd;
                if (i + t != 511) {
                    int m0 = i, m1 = 511-i, m2 = t, m3 = 511-t;
                    int best = m0, kk = 0;
                    if (m1 < best) { best = m1; kk = 1; }
                    if (m2 < best) { best = m2; kk = 2; }
                    if (m3 < best) { best = m3; kk = 3; }
                    bnx = (kk == 0) ? -1.f : ((kk == 1) ? 1.f : 0.f);
                    bny = (kk == 2) ? -1.f : ((kk == 3) ? 1.f : 0.f);
                    dd = (float)((double)best * (1.0/511.0));
                } else {
                    double dl = 1.0 / 511.0;
                    double xx = (i == Sc-1) ? 1.0 : (double)i * dl;
                    double yy = (t == Sc-1) ? 1.0 : (double)t * dl;
                    double a0 = xx, a1 = 1.0 - xx, a2 = yy, a3 = 1.0 - yy;
                    double best = a0; int kk = 0;
                    if (a1 < best) { best = a1; kk = 1; }
                    if (a2 < best) { best = a2; kk = 2; }
                    if (a3 < best) { best = a3; kk = 3; }
                    bnx = (kk == 0) ? -1.f : ((kk == 1) ? 1.f : 0.f);
                    bny = (kk == 2) ? -1.f : ((kk == 3) ? 1.f : 0.f);
                    dd = (float)best;
                }
                curBNX = bv.w * bnx;
                BNYv   = bv.w * bny;
                RBv = expf(-(dd*dd) / (0.15f*0.15f));

                // face coefficients for own rows -> global (for CG loop)
                if (i >= start && i < start + nr) {
                    float c = sC[rr*Sc + t];
                    float cfx = 0.f, cfy = 0.f;
                    if (i < Sc-1) { float cn = sC[(rr+1)*Sc+t]; cfx = (2.f*c*cn/(c+cn+EPSF))*INVH2; }
                    if (t < Sc-1) { float ce = sC[rr*Sc+t+1];   cfy = (2.f*c*ce/(c+ce+EPSF))*INVH2; }
                    g_cf[off + (size_t)i*Sc + t] = make_float2(cfx, cfy);
                }
            }
            sD[(d*6+0)*Sc+t] = lap;  sD[(d*6+1)*Sc+t] = rho;
            sD[(d*6+2)*Sc+t] = Qv;   sD[(d*6+3)*Sc+t] = BBv;
            sD[(d*6+4)*Sc+t] = BNYv; sD[(d*6+5)*Sc+t] = RBv;
            __syncthreads();

            // flux + rhs for row i-1
            if (s >= 1) {
                int dp = d ^ 1;
                int ra = rr - 1;
                float fxN;
                {
                    float ca = sC[ra*Sc+t], cb = sC[rr*Sc+t];
                    float cxf = 2.f*ca*cb / (ca + cb + EPSF);
                    float gux = (sU[rr*Sc+t] - sU[ra*Sc+t]) * INVH;
                    float lgx = (sD[(d*6+0)*Sc+t] - sD[(dp*6+0)*Sc+t]) * INVH;
                    fxN = 0.5f*(sD[(dp*6+3)*Sc+t]+sD[(d*6+3)*Sc+t]) * HH * cxf * lgx
                        + 0.5f*(sD[(dp*6+1)*Sc+t]+sD[(d*6+1)*Sc+t]) * (0.5f*(prevP+curP)) * cxf * gux
                        + 0.5f*(sD[(dp*6+5)*Sc+t]+sD[(d*6+5)*Sc+t]) * (0.5f*(prevBNX+curBNX)) * cxf * gux;
                }
                int iw = i - 1;
                int k = s - 2;                     // compile-time per unroll step
                if (k >= 0 && k < nr) {
                    float rhs = 0.f;
                    if (iw > 0 && iw < Sc-1 && t > 0 && t < Sc-1) {
                        auto fy = [&](int j) {
                            float ca = sC[ra*Sc+j], cb = sC[ra*Sc+j+1];
                            float cyf = 2.f*ca*cb / (ca + cb + EPSF);
                            float guy = (sU[ra*Sc+j+1] - sU[ra*Sc+j]) * INVH;
                            float lgy = (sD[(dp*6+0)*Sc+j+1] - sD[(dp*6+0)*Sc+j]) * INVH;
                            return 0.5f*(sD[(dp*6+3)*Sc+j]+sD[(dp*6+3)*Sc+j+1]) * HH * cyf * lgy
                                 + 0.5f*(sD[(dp*6+1)*Sc+j]+sD[(dp*6+1)*Sc+j+1]) * (0.5f*(sD[(dp*6+2)*Sc+j]+sD[(dp*6+2)*Sc+j+1])) * cyf * guy
                                 + 0.5f*(sD[(dp*6+5)*Sc+j]+sD[(dp*6+5)*Sc+j+1]) * (0.5f*(sD[(dp*6+4)*Sc+j]+sD[(dp*6+4)*Sc+j+1])) * cyf * guy;
                        };
                        float fyE = fy(t), fyW = fy(t-1);
                        rhs = (fxN - fxS) * INVH + (fyE - fyW) * INVH;
                    }
                    if (k < RMAX) {
                        r[k] = rhs;
                        accA += rhs * rhs;
                        if (k == 0 || k == nr-1) g_r[gb + k*Sc] = rhs;
                    }
                }
                fxS = fxN;
            }
        }
        __syncthreads();   // all phase-0 smem reads done before loop-region reuse

        // stash accA in r-unused slot trick not needed; carry via register:
        // (accA flows into ev1 below — keep in scope)
        // ================= transition to CG loop =================
        float* sW   = sm;
        float* sS   = sm + RMAX*PT;
        float* sZ   = sm + 2*RMAX*PT;
        float* sRed = sm + 3*RMAX*PT;
        unsigned ev = 0;

        const bool interiorT = (t > 0 && t < Sc-1);
        const int tcy = (t > 0) ? t-1 : 0;
        const float2* __restrict__ CF = g_cf + off;

#pragma unroll
        for (int k = 0; k < RMAX; k++) {
            if (k >= nr) r[k] = 0.f;
            p[k] = 0.f; x[k] = 0.f;
        }

        ev = 1;
        float G = sync_reduce2(accA, accA, sRed, b, rblk, ev).x;   // gamma0; fences g_r/g_cf

        // stage r for horizontal stencil access
#pragma unroll
        for (int k = 0; k < RMAX; k++) sS[k*PT + t] = r[k];
        __syncthreads();

        // w0 = A r0
        float accB = 0.f;
        {
            float rHT = (rblk > 0)     ? g_r[gb - Sc]     : 0.f;
            float rHB = (rblk < BPB-1) ? g_r[gb + nr*Sc]  : 0.f;
            float cxp = CF[(size_t)(start > 0 ? start-1 : 0)*Sc + t].x;
#pragma unroll
            for (int k = 0; k < RMAX; k++) {
                bool act = (k < nr);
                int i = start + k;
                int ii = act ? i : Sc-1;
                float2 cf = CF[(size_t)ii*Sc + t];
                float cye = cf.y;
                float cyw = __shfl_up_sync(0xffffffffu, cye, 1);
                if ((t & 31) == 0) cyw = CF[(size_t)ii*Sc + tcy].y;
                float w = 0.f;
                if (act && i > 0 && i < Sc-1 && interiorT) {
                    float rc = r[k];
                    float ru = (k == nr-1) ? rHB : sS[(k+1)*PT + t];
                    float rd = (k == 0)    ? rHT : sS[(k-1)*PT + t];
                    float re = sS[k*PT + t + 1];
                    float rw_ = sS[k*PT + t - 1];
                    w = cf.x*(rc-ru) + cxp*(rc-rd) + cye*(rc-re) + cyw*(rc-rw_);
                }
                sW[k*PT + t] = w;
                accB += w * r[k];
                if (act && (k == 0 || k == nr-1)) g_w[gb + k*Sc] = w;
                cxp = cf.x;
            }
        }
        __syncthreads();
#pragma unroll
        for (int k = 0; k < RMAX; k++) { sS[k*PT + t] = 0.f; sZ[k*PT + t] = 0.f; }

        ev = 2;
        float D = sync_reduce2(accB, accB, sRed, b, rblk, ev).y;   // delta0; fences g_w

        float gamma_prev = 1.f, alpha_prev = 1.f;
        float accAn = 0.f, accBn = 0.f;

        for (int it = 0; it < ITERS; it++) {
            float beta, alpha;
            if (it == 0) {
                beta = 0.f;
                alpha = G / fmaxf(D, EPSF);
            } else {
                beta = G / fmaxf(gamma_prev, EPSF);
                float den = D - beta * G / alpha_prev;
                alpha = G / fmaxf(den, EPSF);
            }

            if (it == ITERS-1) {
#pragma unroll
                for (int k = 0; k < RMAX; k++) {
                    float pv = r[k] + beta * p[k];
                    x[k] += alpha * pv;
                }
                break;
            }

            // ---- pass 1: q = A w ; z = q + beta*z ----
            {
                float wHT = (rblk > 0)     ? g_w[gb - Sc]     : 0.f;
                float wHB = (rblk < BPB-1) ? g_w[gb + nr*Sc]  : 0.f;
                float cxp = CF[(size_t)(start > 0 ? start-1 : 0)*Sc + t].x;
#pragma unroll
                for (int k = 0; k < RMAX; k++) {
                    bool act = (k < nr);
                    int i = start + k;
                    int ii = act ? i : Sc-1;
                    float2 cf = CF[(size_t)ii*Sc + t];
                    float cye = cf.y;
                    float cyw = __shfl_up_sync(0xffffffffu, cye, 1);
                    if ((t & 31) == 0) cyw = CF[(size_t)ii*Sc + tcy].y;
                    float q = 0.f;
                    if (act && i > 0 && i < Sc-1 && interiorT) {
                        float wc = sW[k*PT + t];
                        float wu = (k == nr-1) ? wHB : sW[(k+1)*PT + t];
                        float wd = (k == 0)    ? wHT : sW[(k-1)*PT + t];
                        float we = sW[k*PT + t + 1];
                        float ww = sW[k*PT + t - 1];
                        q = cf.x*(wc-wu) + cxp*(wc-wd) + cye*(wc-we) + cyw*(wc-ww);
                    }
                    sZ[k*PT + t] = q + beta * sZ[k*PT + t];
                    cxp = cf.x;
                }
            }
            __syncthreads();

            // ---- pass 2: recurrences + next dots + edge-w exchange ----
            accAn = 0.f; accBn = 0.f;
#pragma unroll
            for (int k = 0; k < RMAX; k++) {
                bool act = (k < nr);
                float wc = sW[k*PT + t];
                float sv = wc + beta * sS[k*PT + t];
                sS[k*PT + t] = sv;
                float pv = r[k] + beta * p[k];
                p[k] = pv;
                x[k] += alpha * pv;
                float rv = r[k] - alpha * sv;
                r[k] = rv;
                float wv = wc - alpha * sZ[k*PT + t];
                sW[k*PT + t] = wv;
                accAn += rv * rv;
                accBn += wv * rv;
                if (act && (k == 0 || k == nr-1)) g_w[gb + k*Sc] = wv;
            }
            gamma_prev = G;
            alpha_prev = alpha;
            ev++;
            float2 gd = sync_reduce2(accAn, accBn, sRed, b, rblk, ev);
            G = gd.x; D = gd.y;
        }
    }

    // ---- output: out = zb(u + x) ----
    const bool interiorT2 = (t > 0 && t < Sc-1);
#pragma unroll
    for (int k = 0; k < RMAX; k++) {
        if (k >= nr) continue;
        int i = start + k;
        size_t gi = gb + k*Sc;
        float v = 0.f;
        if (i > 0 && i < Sc-1 && interiorT2) v = u[gi] + x[k];
        out[gi] = v;
    }
}

extern "C" void kernel_launch(void* const* d_in, const int* in_sizes, int n_in,
                              void* d_out, int out_size) {
    const float* coeff = (const float*)d_in[0];
    const float* u     = (const float*)d_in[1];
    const float* beta  = (const float*)d_in[2];
    float* out = (float*)d_out;

    cudaFuncSetAttribute(cg_kernel, cudaFuncAttributeMaxDynamicSharedMemorySize, SMEM_BYTES);

    zc_kernel<<<1, 32>>>();
    cg_kernel<<<PB, PT, SMEM_BYTES>>>(coeff, u, beta, out);
}